// round 9
// baseline (speedup 1.0000x reference)
#include <cuda_runtime.h>
#include <cuda_bf16.h>
#include <cstdint>

// ---------------------------------------------------------------------------
// WaveFDTD2D, temporal blocking K=4, 128 persistent CTAs x 512 threads.
// CONSECUTIVE-row ownership: thread (tx,ty) owns rows {3ty, 3ty+1, 3ty+2};
// middle row's up/down neighbors live in this thread's registers, so each
// substep needs only TWO edge float4 LDS per thread (vs 6 with strided rows).
// m (current), o (old), cf (v^2 dt^2) in registers for the whole K=4 block.
// SMEM: 2 ping-pong field images for cross-thread neighbor reads.
// Neighbor-only inter-CTA sync via monotonic per-CTA counters.
// ---------------------------------------------------------------------------

#define NX      512
#define NZ      512
#define NSTEPS  512
#define NREC    128
#define KST     4
#define NBLK    (NSTEPS / KST)     // 128
#define NCTA    128
#define NTHR    512
#define RROWS   4
#define EXT     12                 // SMEM image rows 0..11
#define SROW    520
#define BUF     (EXT * SROW)
#define SMEM_FLOATS (2 * BUF)      // S0, S1
#define SMEM_BYTES  (SMEM_FLOATS * 4)
#define PAD     32

__device__ __align__(16) float g_P[2][NX * NZ];
__device__ __align__(16) float g_Q[2][NX * NZ];
__device__ unsigned long long g_done[NCTA * PAD];   // monotonic, never reset

static __device__ __forceinline__ void signal_done(int bid) {
    asm volatile("red.add.release.gpu.u64 [%0], 1;"
                 :: "l"(&g_done[bid * PAD]) : "memory");
}

static __device__ __forceinline__ void wait_neighbors(int bid, unsigned long long tgt) {
    const unsigned long long* lo =
        (bid > 0) ? &g_done[(bid - 1) * PAD] : nullptr;
    const unsigned long long* hi =
        (bid < NCTA - 1) ? &g_done[(bid + 1) * PAD] : nullptr;
    bool need_lo = (lo != nullptr), need_hi = (hi != nullptr);
    while (need_lo || need_hi) {
        unsigned long long a = tgt, b = tgt;
        if (need_lo)
            asm volatile("ld.acquire.gpu.u64 %0, [%1];" : "=l"(a) : "l"(lo) : "memory");
        if (need_hi)
            asm volatile("ld.acquire.gpu.u64 %0, [%1];" : "=l"(b) : "l"(hi) : "memory");
        if (a >= tgt) need_lo = false;
        if (b >= tgt) need_hi = false;
    }
}

// Core 4-wide stencil: reference-order arithmetic.
static __device__ __forceinline__ float4 stencil4(
    const float4 mc, const float4 u, const float4 d,
    const float lf, const float rg, const float4 o, const float4 cf)
{
    const float INV = 0.01f;   // 1/(dx*dz)
    float4 nw; float lap;
    lap  = ((((u.x + d.x) + lf)   + mc.y) - 4.0f * mc.x) * INV;
    nw.x = (2.0f * mc.x - o.x) + cf.x * lap;
    lap  = ((((u.y + d.y) + mc.x) + mc.z) - 4.0f * mc.y) * INV;
    nw.y = (2.0f * mc.y - o.y) + cf.y * lap;
    lap  = ((((u.z + d.z) + mc.y) + mc.w) - 4.0f * mc.z) * INV;
    nw.z = (2.0f * mc.z - o.z) + cf.z * lap;
    lap  = ((((u.w + d.w) + mc.z) + rg)   - 4.0f * mc.w) * INV;
    nw.w = (2.0f * mc.w - o.w) + cf.w * lap;
    return nw;
}

// One substep over rows [LO,HI]. Thread owns rows i0..i0+2 (i0 = 3*ty).
// Edge rows load u/d from Scur; middle row uses register neighbors.
template<int LO, int HI, bool STORE>
static __device__ __forceinline__ void substep(
    const float* __restrict__ Scur, float* __restrict__ Snext,
    float4 (&m)[3], float4 (&o)[3], const float4 (&cf)[3],
    int clo, int chi, int g0, int tx, int ty,
    int sx, int sz, const float* __restrict__ source, int t,
    float* __restrict__ gdst)
{
    const float DT2f = 1.0e-6f;
    const int colbase = 4 + tx * 4;
    const int i0 = 3 * ty;
    const int b0 = i0 * SROW + colbase;

    const bool v0 = (i0     >= LO) && (i0     <= HI) && (i0     >= clo) && (i0     <= chi);
    const bool v1 = (i0 + 1 >= LO) && (i0 + 1 <= HI) && (i0 + 1 >= clo) && (i0 + 1 <= chi);
    const bool v2 = (i0 + 2 >= LO) && (i0 + 2 <= HI) && (i0 + 2 >= clo) && (i0 + 2 <= chi);

    // ---- issue all SMEM loads up front ----
    float4 u0, d2;
    float lf0 = 0.f, rg0 = 0.f, lf1 = 0.f, rg1 = 0.f, lf2 = 0.f, rg2 = 0.f;
    if (v0) {
        u0  = *reinterpret_cast<const float4*>(Scur + b0 - SROW);
        lf0 = Scur[b0 - 1];
        rg0 = Scur[b0 + 4];
    }
    if (v1) {
        lf1 = Scur[b0 + SROW - 1];
        rg1 = Scur[b0 + SROW + 4];
    }
    if (v2) {
        d2  = *reinterpret_cast<const float4*>(Scur + b0 + 3 * SROW);
        lf2 = Scur[b0 + 2 * SROW - 1];
        rg2 = Scur[b0 + 2 * SROW + 4];
    }

    const float4 mm0 = m[0], mm1 = m[1], mm2 = m[2];
    const bool src_col = ((sz >> 2) == tx);
    const int  src_lane = sz & 3;

    // middle row first (no LDS dependency -> overlaps edge loads)
    if (v1) {
        float4 nw = stencil4(mm1, mm0, mm2, lf1, rg1, o[1], cf[1]);
        const int g = g0 - 4 + i0 + 1;
        if (g == sx && src_col) {
            const float sadd = __ldg(source + t) * DT2f;
            nw.x += (src_lane == 0) ? sadd : 0.0f;
            nw.y += (src_lane == 1) ? sadd : 0.0f;
            nw.z += (src_lane == 2) ? sadd : 0.0f;
            nw.w += (src_lane == 3) ? sadd : 0.0f;
        }
        *reinterpret_cast<float4*>(Snext + b0 + SROW) = nw;
        if (STORE && (i0 + 1) >= 4 && (i0 + 1) <= 7)
            __stcg(reinterpret_cast<float4*>(gdst + (size_t)g * NZ + tx * 4), nw);
        o[1] = mm1; m[1] = nw;
    }
    if (v0) {
        float4 nw = stencil4(mm0, u0, mm1, lf0, rg0, o[0], cf[0]);
        const int g = g0 - 4 + i0;
        if (g == sx && src_col) {
            const float sadd = __ldg(source + t) * DT2f;
            nw.x += (src_lane == 0) ? sadd : 0.0f;
            nw.y += (src_lane == 1) ? sadd : 0.0f;
            nw.z += (src_lane == 2) ? sadd : 0.0f;
            nw.w += (src_lane == 3) ? sadd : 0.0f;
        }
        *reinterpret_cast<float4*>(Snext + b0) = nw;
        if (STORE && i0 >= 4 && i0 <= 7)
            __stcg(reinterpret_cast<float4*>(gdst + (size_t)g * NZ + tx * 4), nw);
        o[0] = mm0; m[0] = nw;
    }
    if (v2) {
        float4 nw = stencil4(mm2, mm1, d2, lf2, rg2, o[2], cf[2]);
        const int g = g0 - 4 + i0 + 2;
        if (g == sx && src_col) {
            const float sadd = __ldg(source + t) * DT2f;
            nw.x += (src_lane == 0) ? sadd : 0.0f;
            nw.y += (src_lane == 1) ? sadd : 0.0f;
            nw.z += (src_lane == 2) ? sadd : 0.0f;
            nw.w += (src_lane == 3) ? sadd : 0.0f;
        }
        *reinterpret_cast<float4*>(Snext + b0 + 2 * SROW) = nw;
        if (STORE && (i0 + 2) >= 4 && (i0 + 2) <= 7)
            __stcg(reinterpret_cast<float4*>(gdst + (size_t)g * NZ + tx * 4), nw);
        o[2] = mm2; m[2] = nw;
    }
}

__global__ void __launch_bounds__(NTHR, 1)
wave_fdtd_reg_kernel(const float* __restrict__ vel,
                     const float* __restrict__ source,
                     const int*   __restrict__ p_srcx,
                     const int*   __restrict__ p_srcz,
                     const int*   __restrict__ rec_x,
                     const int*   __restrict__ rec_z,
                     float*       __restrict__ out)
{
    extern __shared__ float sm[];
    __shared__ unsigned long long sm_base;
    float* S0 = sm;           // p_n at block entry / p_{n+4} at exit
    float* S1 = sm + BUF;

    const int tid = threadIdx.x;
    const int bid = blockIdx.x;
    const int g0  = bid * RROWS;
    const int tx  = tid & 127;
    const int ty  = tid >> 7;    // 0..3 -> rows {3ty, 3ty+1, 3ty+2}
    const int colbase = 4 + tx * 4;

    const int sx = p_srcx[0];
    const int sz = p_srcz[0];

    const int clo = 4 - g0;        // min valid SMEM row
    const int chi = 515 - g0;      // max valid SMEM row

    int my_rx = -1, my_rz = 0;
    if (tid < NREC) { my_rx = __ldg(rec_x + tid); my_rz = __ldg(rec_z + tid); }
    const bool my_rec = (my_rx >= 0) && ((my_rx >> 2) == bid);
    const int  rec_off = my_rec ? ((4 + (my_rx & 3)) * SROW + 4 + my_rz) : 0;

    // ---- zero SMEM; read own counter base ----
    for (int i = tid; i < SMEM_FLOATS; i += NTHR) sm[i] = 0.0f;
    if (tid == 0) sm_base = g_done[bid * PAD];
    __syncthreads();
    const unsigned long long base = sm_base;

    // ---- register state init ----
    const float DT2f = 1.0e-6f;
    float4 m[3], o[3], cf[3];
    #pragma unroll
    for (int k = 0; k < 3; ++k) {
        m[k] = make_float4(0.f, 0.f, 0.f, 0.f);
        o[k] = make_float4(0.f, 0.f, 0.f, 0.f);
        const int i = 3 * ty + k;
        const int g = g0 - 4 + i;
        if ((unsigned)g < (unsigned)NX) {
            const float4 v = __ldg(reinterpret_cast<const float4*>(
                                   vel + (size_t)g * NZ + tx * 4));
            cf[k] = make_float4(v.x * v.x * DT2f, v.y * v.y * DT2f,
                                v.z * v.z * DT2f, v.w * v.w * DT2f);
        } else {
            cf[k] = make_float4(0.f, 0.f, 0.f, 0.f);
        }
    }

    // ---- zero OWN rows of global pair 0 (stale from prior replay) ----
    {
        const float4 z = make_float4(0.f, 0.f, 0.f, 0.f);
        for (int idx = tid; idx < RROWS * 128; idx += NTHR) {
            const int r = idx >> 7, c = idx & 127;
            const size_t off = (size_t)(g0 + r) * NZ + c * 4;
            __stcg(reinterpret_cast<float4*>(g_P[0] + off), z);
            __stcg(reinterpret_cast<float4*>(g_Q[0] + off), z);
        }
    }
    __syncthreads();
    if (tid == 0) signal_done(bid);   // counter -> base+1

    for (int b = 0; b < NBLK; ++b) {
        if (tid == 0)
            wait_neighbors(bid, base + 1 + (unsigned long long)b);
        __syncthreads();

        const int pb = b & 1;
        const float* gp = g_P[pb];
        const float* gq = g_Q[pb];

        // ---- halo refresh: rows outside [4,7] reload m (and o) ----
        #pragma unroll
        for (int k = 0; k < 3; ++k) {
            const int i = 3 * ty + k;
            if (i >= 4 && i <= 7) continue;     // own interior rows persist
            const int g = g0 - 4 + i;
            if ((unsigned)g < (unsigned)NX) {
                const float4 v = __ldcg(reinterpret_cast<const float4*>(
                                        gp + (size_t)g * NZ + tx * 4));
                if (i == 3 || i == 8) {
                    o[k] = m[k];                // p_{n-1} computed here at prev s3
                } else if (i == 1 || i == 2 || i == 9 || i == 10) {
                    o[k] = __ldcg(reinterpret_cast<const float4*>(
                                  gq + (size_t)g * NZ + tx * 4));
                }
                m[k] = v;
                *reinterpret_cast<float4*>(S0 + i * SROW + colbase) = v;
            }
        }
        __syncthreads();

        const int t0 = b * KST;
        float* gpo = g_P[pb ^ 1];
        float* gqo = g_Q[pb ^ 1];

        // s1: p_{n+1}, rows [1,10], S0 -> S1
        substep<1, 10, false>(S0, S1, m, o, cf, clo, chi, g0, tx, ty,
                              sx, sz, source, t0, nullptr);
        __syncthreads();
        if (my_rec) out[(size_t)tid * NSTEPS + t0] = S1[rec_off];

        // s2: p_{n+2}, rows [2,9], S1 -> S0
        substep<2, 9, false>(S1, S0, m, o, cf, clo, chi, g0, tx, ty,
                             sx, sz, source, t0 + 1, nullptr);
        __syncthreads();
        if (my_rec) out[(size_t)tid * NSTEPS + t0 + 1] = S0[rec_off];

        // s3: p_{n+3}, rows [3,8], S0 -> S1; own rows -> Q[pb^1]
        substep<3, 8, true>(S0, S1, m, o, cf, clo, chi, g0, tx, ty,
                            sx, sz, source, t0 + 2, gqo);
        __syncthreads();
        if (my_rec) out[(size_t)tid * NSTEPS + t0 + 2] = S1[rec_off];

        // s4: p_{n+4}, rows [4,7], S1 -> S0; own rows -> P[pb^1]
        substep<4, 7, true>(S1, S0, m, o, cf, clo, chi, g0, tx, ty,
                            sx, sz, source, t0 + 3, gpo);
        __syncthreads();
        if (my_rec) out[(size_t)tid * NSTEPS + t0 + 3] = S0[rec_off];

        if (tid == 0) signal_done(bid);   // counter -> base+2+b
    }
}

extern "C" void kernel_launch(void* const* d_in, const int* in_sizes, int n_in,
                              void* d_out, int out_size)
{
    const float* vel    = (const float*)d_in[0];
    const float* source = (const float*)d_in[1];
    const int*   srcx   = (const int*)d_in[2];
    const int*   srcz   = (const int*)d_in[3];
    const int*   rec_x  = (const int*)d_in[4];
    const int*   rec_z  = (const int*)d_in[5];
    float* out = (float*)d_out;

    cudaFuncSetAttribute(wave_fdtd_reg_kernel,
                         cudaFuncAttributeMaxDynamicSharedMemorySize, SMEM_BYTES);
    wave_fdtd_reg_kernel<<<NCTA, NTHR, SMEM_BYTES>>>(
        vel, source, srcx, srcz, rec_x, rec_z, out);
}